// round 5
// baseline (speedup 1.0000x reference)
#include <cuda_runtime.h>

#define BB 8
#define NN 20000
#define DD 640
#define RR 2500
#define BINS 10
#define HID 128
#define EPSV 1e-5f

typedef unsigned long long ull;

// ---------------- scratch (no allocation allowed) ----------------
__device__ float g_pooled[RR * BB * BINS];   // [r][b][bin] segment sums
__device__ int   g_off[RR + 1];              // segment offsets (res_id sorted)
__device__ float g_sum[HID];
__device__ float g_sumsq[HID];
__device__ float g_W2p[HID * 3];             // layernorm-scaled W2
__device__ float g_b2p[3];                   // folded output bias

// ---------------- packed f32x2 helpers (sm_100+) ----------------
__device__ __forceinline__ ull pk2(float lo, float hi) {
    ull r; asm("mov.b64 %0,{%1,%2};" : "=l"(r) : "f"(lo), "f"(hi)); return r;
}
__device__ __forceinline__ void upk2(ull v, float& lo, float& hi) {
    asm("mov.b64 {%0,%1},%2;" : "=f"(lo), "=f"(hi) : "l"(v));
}
__device__ __forceinline__ ull add2(ull a, ull b) {
    ull d; asm("add.rn.f32x2 %0,%1,%2;" : "=l"(d) : "l"(a), "l"(b)); return d;
}
__device__ __forceinline__ ull mul2(ull a, ull b) {
    ull d; asm("mul.rn.f32x2 %0,%1,%2;" : "=l"(d) : "l"(a), "l"(b)); return d;
}
__device__ __forceinline__ ull fma2(ull a, ull b, ull c) {
    ull d; asm("fma.rn.f32x2 %0,%1,%2,%3;" : "=l"(d) : "l"(a), "l"(b), "l"(c)); return d;
}
// relu on a packed pair: unpack (reg-rename), 2x FMNMX, repack (rename)
__device__ __forceinline__ ull relu2(ull a) {
    float lo, hi; upk2(a, lo, hi);
    return pk2(fmaxf(lo, 0.0f), fmaxf(hi, 0.0f));
}

// ---------------- K0: zero accumulators + segment offsets ----------------
__global__ void k_init(const int* __restrict__ res_id) {
    int i = blockIdx.x * blockDim.x + threadIdx.x;
    if (i < RR * BB * BINS) g_pooled[i] = 0.0f;
    if (i < NN) {
        int r = res_id[i];
        if (i == 0 || res_id[i - 1] != r) g_off[r] = i;
    }
    if (i == 0) g_off[RR] = NN;
    if (i < HID) { g_sum[i] = 0.0f; g_sumsq[i] = 0.0f; }
}

// ---------------- K1: pooling (dominant, reads all 410MB of x) ----------------
// One warp per (b, atom) row: 160 float4, fully coalesced. Lane l handles
// float4 items l, l+32k; item i -> bin i/16, the two 16-lane halves each own
// 5 fixed bins; 16-lane shuffle reduce, then 10 atomics/row over 200K addrs.
__global__ void k_pool(const float4* __restrict__ x4, const int* __restrict__ res_id) {
    int w = (blockIdx.x * blockDim.x + threadIdx.x) >> 5;
    int lane = threadIdx.x & 31;
    if (w >= BB * NN) return;
    int b = w / NN;
    int n = w - b * NN;
    int rid = res_id[n];
    const float4* row = x4 + (size_t)w * (DD / 4);

    float s[5];
#pragma unroll
    for (int k = 0; k < 5; k++) {
        float4 v = __ldg(&row[lane + 32 * k]);
        s[k] = (v.x + v.y) + (v.z + v.w);
    }
#pragma unroll
    for (int k = 0; k < 5; k++) {
#pragma unroll
        for (int off = 8; off >= 1; off >>= 1)
            s[k] += __shfl_down_sync(0xffffffffu, s[k], off, 16);
    }
    if ((lane & 15) == 0) {
        int half = lane >> 4;
        float* dst = &g_pooled[((size_t)rid * BB + b) * BINS];
#pragma unroll
        for (int k = 0; k < 5; k++)
            atomicAdd(&dst[2 * k + half], s[k]);
    }
}

// Shared prologue: packed W1 with feature pairing (lane,lane+32)->k2=0,
// (lane+64,lane+96)->k2=1.
#define LOAD_W1_PACKED()                                                        \
    ull w1p2[BINS][2], w1c2[3][2], bb2[2];                                      \
    _Pragma("unroll")                                                           \
    for (int j = 0; j < BINS; j++) {                                            \
        w1p2[j][0] = pk2(__ldg(&W1[j * HID + lane]), __ldg(&W1[j * HID + lane + 32]));       \
        w1p2[j][1] = pk2(__ldg(&W1[j * HID + lane + 64]), __ldg(&W1[j * HID + lane + 96]));  \
    }                                                                           \
    _Pragma("unroll")                                                           \
    for (int j = 0; j < 3; j++) {                                               \
        w1c2[j][0] = pk2(__ldg(&W1[(BINS + j) * HID + lane]), __ldg(&W1[(BINS + j) * HID + lane + 32]));      \
        w1c2[j][1] = pk2(__ldg(&W1[(BINS + j) * HID + lane + 64]), __ldg(&W1[(BINS + j) * HID + lane + 96])); \
    }                                                                           \
    bb2[0] = pk2(__ldg(&b1[lane]), __ldg(&b1[lane + 32]));                      \
    bb2[1] = pk2(__ldg(&b1[lane + 64]), __ldg(&b1[lane + 96]));

// Per-residue a2[b][k2] from pooled sums (mean over FULL segment count), plus
// this warp's half of the atom range [lo, hi).
#define COMPUTE_A2()                                                            \
    int o0 = g_off[r], o1 = g_off[r + 1], cnt = o1 - o0;                        \
    int lo = o0 + ((cnt * half) >> 1), hi = o0 + ((cnt * (half + 1)) >> 1);     \
    int subcnt = hi - lo;                                                       \
    float inv = 1.0f / ((float)cnt * 64.0f);                                    \
    const float* pp = &g_pooled[(size_t)r * BB * BINS];                         \
    float p0 = pp[lane], p1 = pp[lane + 32], p2 = (lane < 16) ? pp[lane + 64] : 0.0f; \
    ull a2[BB][2];                                                              \
    _Pragma("unroll")                                                           \
    for (int b = 0; b < BB; b++) {                                              \
        a2[b][0] = bb2[0]; a2[b][1] = bb2[1];                                   \
        _Pragma("unroll")                                                       \
        for (int j = 0; j < BINS; j++) {                                        \
            int idx = b * BINS + j;                                             \
            float v = __shfl_sync(0xffffffffu, idx < 32 ? p0 : (idx < 64 ? p1 : p2), idx & 31); \
            float pm = v * inv;                                                 \
            ull pm2 = pk2(pm, pm);                                              \
            a2[b][0] = fma2(pm2, w1p2[j][0], a2[b][0]);                         \
            a2[b][1] = fma2(pm2, w1p2[j][1], a2[b][1]);                         \
        }                                                                       \
    }

// ---------------- K2: per-feature sum / sumsq of relu(h) ----------------
// Two warps per residue (atom range split); all 8 batches share cond loads.
__global__ void __launch_bounds__(128) k_stats(const float* __restrict__ cond,
                                               const float* __restrict__ W1,
                                               const float* __restrict__ b1) {
    __shared__ float ssum[HID];
    __shared__ float ssq[HID];
    int t = threadIdx.x;
    ssum[t] = 0.0f; ssq[t] = 0.0f;
    __syncthreads();
    int lane = t & 31;

    LOAD_W1_PACKED();

    ull ls2[2] = {0, 0}, lq2[2] = {0, 0};
    int wg = (blockIdx.x * blockDim.x + t) >> 5;   // 0 .. 2*RR-1
    int r = wg >> 1, half = wg & 1;
    if (r < RR) {
        COMPUTE_A2();
        // segment halves are <=5 atoms -> 15 floats fit in one warp load
        float cseg = (lane < 3 * subcnt) ? __ldg(&cond[lo * 3 + lane]) : 0.0f;
        for (int i = 0; i < subcnt; i++) {
            float c0 = __shfl_sync(0xffffffffu, cseg, 3 * i);
            float c1 = __shfl_sync(0xffffffffu, cseg, 3 * i + 1);
            float c2 = __shfl_sync(0xffffffffu, cseg, 3 * i + 2);
            ull c02 = pk2(c0, c0), c12 = pk2(c1, c1), c22 = pk2(c2, c2);
#pragma unroll
            for (int k2 = 0; k2 < 2; k2++) {
                ull cc = fma2(c02, w1c2[0][k2], fma2(c12, w1c2[1][k2], mul2(c22, w1c2[2][k2])));
#pragma unroll
                for (int b = 0; b < BB; b++) {
                    ull v = relu2(add2(a2[b][k2], cc));
                    ls2[k2] = add2(ls2[k2], v);
                    lq2[k2] = fma2(v, v, lq2[k2]);
                }
            }
        }
    }
    float x0, x1;
    upk2(ls2[0], x0, x1); atomicAdd(&ssum[lane], x0); atomicAdd(&ssum[lane + 32], x1);
    upk2(ls2[1], x0, x1); atomicAdd(&ssum[lane + 64], x0); atomicAdd(&ssum[lane + 96], x1);
    upk2(lq2[0], x0, x1); atomicAdd(&ssq[lane], x0);  atomicAdd(&ssq[lane + 32], x1);
    upk2(lq2[1], x0, x1); atomicAdd(&ssq[lane + 64], x0); atomicAdd(&ssq[lane + 96], x1);
    __syncthreads();
    atomicAdd(&g_sum[t], ssum[t]);
    atomicAdd(&g_sumsq[t], ssq[t]);
}

// ---------------- K3: fold layernorm into W2/b2 (1 block) ----------------
__global__ void k_final(const float* __restrict__ gamma, const float* __restrict__ beta,
                        const float* __restrict__ W2, const float* __restrict__ b2) {
    int f = threadIdx.x;  // 128
    const float inv = 1.0f / (float)(BB * NN);
    float mu = g_sum[f] * inv;
    float var = g_sumsq[f] * inv - mu * mu;
    float s = rsqrtf(var + EPSV) * gamma[f];
    float off = beta[f] - mu * s;
    float w0 = W2[f * 3 + 0], w1 = W2[f * 3 + 1], w2 = W2[f * 3 + 2];
    g_W2p[f * 3 + 0] = w0 * s;
    g_W2p[f * 3 + 1] = w1 * s;
    g_W2p[f * 3 + 2] = w2 * s;

    __shared__ float red[3][HID];
    red[0][f] = off * w0;
    red[1][f] = off * w1;
    red[2][f] = off * w2;
    __syncthreads();
    for (int st = 64; st >= 1; st >>= 1) {
        if (f < st) {
            red[0][f] += red[0][f + st];
            red[1][f] += red[1][f + st];
            red[2][f] += red[2][f + st];
        }
        __syncthreads();
    }
    if (f < 3) g_b2p[f] = b2[f] + red[f][0];
}

// ---------------- K4: output = relu(h) @ W2p + b2p ----------------
// Two warps per residue (atom range split).
__global__ void __launch_bounds__(128) k_out(const float* __restrict__ cond,
                                             const float* __restrict__ W1,
                                             const float* __restrict__ b1,
                                             float* __restrict__ out) {
    int t = threadIdx.x, lane = t & 31;

    ull w22[2][3];
#pragma unroll
    for (int k2 = 0; k2 < 2; k2++)
#pragma unroll
        for (int j = 0; j < 3; j++)
            w22[k2][j] = pk2(g_W2p[(lane + 64 * k2) * 3 + j],
                             g_W2p[(lane + 32 + 64 * k2) * 3 + j]);
    float bo0 = g_b2p[0], bo1 = g_b2p[1], bo2 = g_b2p[2];

    LOAD_W1_PACKED();

    int wg = (blockIdx.x * blockDim.x + t) >> 5;
    int r = wg >> 1, half = wg & 1;
    if (r >= RR) return;
    COMPUTE_A2();
    float cseg = (lane < 3 * subcnt) ? __ldg(&cond[lo * 3 + lane]) : 0.0f;

    for (int i = 0; i < subcnt; i++) {
        float c0 = __shfl_sync(0xffffffffu, cseg, 3 * i);
        float c1 = __shfl_sync(0xffffffffu, cseg, 3 * i + 1);
        float c2 = __shfl_sync(0xffffffffu, cseg, 3 * i + 2);
        ull c02 = pk2(c0, c0), c12 = pk2(c1, c1), c22 = pk2(c2, c2);
        ull cc[2];
#pragma unroll
        for (int k2 = 0; k2 < 2; k2++)
            cc[k2] = fma2(c02, w1c2[0][k2], fma2(c12, w1c2[1][k2], mul2(c22, w1c2[2][k2])));
#pragma unroll
        for (int b = 0; b < BB; b++) {
            ull y0 = 0, y1 = 0, y2v = 0;
#pragma unroll
            for (int k2 = 0; k2 < 2; k2++) {
                ull v = relu2(add2(a2[b][k2], cc[k2]));
                y0 = fma2(v, w22[k2][0], y0);
                y1 = fma2(v, w22[k2][1], y1);
                y2v = fma2(v, w22[k2][2], y2v);
            }
            float u0, u1;
            upk2(y0, u0, u1);  float r0 = u0 + u1;
            upk2(y1, u0, u1);  float r1 = u0 + u1;
            upk2(y2v, u0, u1); float r2 = u0 + u1;
#pragma unroll
            for (int o = 16; o >= 1; o >>= 1) {
                r0 += __shfl_down_sync(0xffffffffu, r0, o);
                r1 += __shfl_down_sync(0xffffffffu, r1, o);
                r2 += __shfl_down_sync(0xffffffffu, r2, o);
            }
            if (lane == 0) {
                float* p = out + ((size_t)b * NN + (lo + i)) * 3;
                p[0] = r0 + bo0;
                p[1] = r1 + bo1;
                p[2] = r2 + bo2;
            }
        }
    }
}

// ---------------- launcher ----------------
extern "C" void kernel_launch(void* const* d_in, const int* in_sizes, int n_in,
                              void* d_out, int out_size) {
    const float* x     = (const float*)d_in[0];
    const float* cond  = (const float*)d_in[1];
    const int*   resid = (const int*)d_in[2];
    const float* W1    = (const float*)d_in[3];
    const float* b1    = (const float*)d_in[4];
    const float* gamma = (const float*)d_in[5];
    const float* beta  = (const float*)d_in[6];
    const float* W2    = (const float*)d_in[7];
    const float* b2    = (const float*)d_in[8];
    float* out = (float*)d_out;

    (void)in_sizes; (void)n_in; (void)out_size;

    k_init<<<(RR * BB * BINS + 255) / 256, 256>>>(resid);
    k_pool<<<(BB * NN + 7) / 8, 256>>>((const float4*)x, resid);
    k_stats<<<(2 * RR * 32 + 127) / 128, 128>>>(cond, W1, b1);
    k_final<<<1, HID>>>(gamma, beta, W2, b2);
    k_out<<<(2 * RR * 32 + 127) / 128, 128>>>(cond, W1, b1, out);
}

// round 6
// speedup vs baseline: 1.0576x; 1.0576x over previous
#include <cuda_runtime.h>

#define BB 8
#define NN 20000
#define DD 640
#define RR 2500
#define BINS 10
#define HID 128
#define EPSV 1e-5f

typedef unsigned long long ull;

// ---------------- scratch (no allocation allowed) ----------------
__device__ float g_pooled[RR * BB * BINS];   // [r][b][bin] segment sums
__device__ int   g_off[RR + 1];              // segment offsets (res_id sorted)
__device__ float g_sum[HID];
__device__ float g_sumsq[HID];
__device__ float g_W2p[HID * 3];             // layernorm-scaled W2
__device__ float g_b2p[3];                   // folded output bias
__device__ unsigned int g_done = 0;          // last-block detector (self-resetting)

// ---------------- packed f32x2 helpers (sm_100+) ----------------
__device__ __forceinline__ ull pk2(float lo, float hi) {
    ull r; asm("mov.b64 %0,{%1,%2};" : "=l"(r) : "f"(lo), "f"(hi)); return r;
}
__device__ __forceinline__ void upk2(ull v, float& lo, float& hi) {
    asm("mov.b64 {%0,%1},%2;" : "=f"(lo), "=f"(hi) : "l"(v));
}
__device__ __forceinline__ ull add2(ull a, ull b) {
    ull d; asm("add.rn.f32x2 %0,%1,%2;" : "=l"(d) : "l"(a), "l"(b)); return d;
}
__device__ __forceinline__ ull mul2(ull a, ull b) {
    ull d; asm("mul.rn.f32x2 %0,%1,%2;" : "=l"(d) : "l"(a), "l"(b)); return d;
}
__device__ __forceinline__ ull fma2(ull a, ull b, ull c) {
    ull d; asm("fma.rn.f32x2 %0,%1,%2,%3;" : "=l"(d) : "l"(a), "l"(b), "l"(c)); return d;
}
__device__ __forceinline__ ull relu2(ull a) {
    float lo, hi; upk2(a, lo, hi);
    return pk2(fmaxf(lo, 0.0f), fmaxf(hi, 0.0f));
}

// ---------------- K0: zero accumulators + segment offsets ----------------
__global__ void k_init(const int* __restrict__ res_id) {
    int i = blockIdx.x * blockDim.x + threadIdx.x;
    if (i < RR * BB * BINS) g_pooled[i] = 0.0f;
    if (i < NN) {
        int r = res_id[i];
        if (i == 0 || res_id[i - 1] != r) g_off[r] = i;
    }
    if (i == 0) g_off[RR] = NN;
    if (i < HID) { g_sum[i] = 0.0f; g_sumsq[i] = 0.0f; }
}

// ---------------- K1: pooling (dominant, reads all 410MB of x) ----------------
// One warp per (b, atom) row: 160 float4, fully coalesced, streaming loads.
__global__ void k_pool(const float4* __restrict__ x4, const int* __restrict__ res_id) {
    int w = (blockIdx.x * blockDim.x + threadIdx.x) >> 5;
    int lane = threadIdx.x & 31;
    if (w >= BB * NN) return;
    int b = w / NN;
    int n = w - b * NN;
    int rid = res_id[n];
    const float4* row = x4 + (size_t)w * (DD / 4);

    float s[5];
#pragma unroll
    for (int k = 0; k < 5; k++) {
        float4 v = __ldcs(&row[lane + 32 * k]);   // read-once: evict-first
        s[k] = (v.x + v.y) + (v.z + v.w);
    }
#pragma unroll
    for (int k = 0; k < 5; k++) {
#pragma unroll
        for (int off = 8; off >= 1; off >>= 1)
            s[k] += __shfl_down_sync(0xffffffffu, s[k], off, 16);
    }
    if ((lane & 15) == 0) {
        int half = lane >> 4;
        float* dst = &g_pooled[((size_t)rid * BB + b) * BINS];
#pragma unroll
        for (int k = 0; k < 5; k++)
            atomicAdd(&dst[2 * k + half], s[k]);
    }
}

// Shared prologue: packed W1, feature pairing (lane,lane+32)->k2=0, (lane+64,lane+96)->k2=1.
#define LOAD_W1_PACKED()                                                        \
    ull w1p2[BINS][2], w1c2[3][2], bb2[2];                                      \
    _Pragma("unroll")                                                           \
    for (int j = 0; j < BINS; j++) {                                            \
        w1p2[j][0] = pk2(__ldg(&W1[j * HID + lane]), __ldg(&W1[j * HID + lane + 32]));       \
        w1p2[j][1] = pk2(__ldg(&W1[j * HID + lane + 64]), __ldg(&W1[j * HID + lane + 96]));  \
    }                                                                           \
    _Pragma("unroll")                                                           \
    for (int j = 0; j < 3; j++) {                                               \
        w1c2[j][0] = pk2(__ldg(&W1[(BINS + j) * HID + lane]), __ldg(&W1[(BINS + j) * HID + lane + 32]));      \
        w1c2[j][1] = pk2(__ldg(&W1[(BINS + j) * HID + lane + 64]), __ldg(&W1[(BINS + j) * HID + lane + 96])); \
    }                                                                           \
    bb2[0] = pk2(__ldg(&b1[lane]), __ldg(&b1[lane + 32]));                      \
    bb2[1] = pk2(__ldg(&b1[lane + 64]), __ldg(&b1[lane + 96]));

// Per-residue a2[b][k2] from pooled sums (mean over FULL segment count), plus
// this warp's half of the atom range [lo, hi).
#define COMPUTE_A2()                                                            \
    int o0 = g_off[r], o1 = g_off[r + 1], cnt = o1 - o0;                        \
    int lo = o0 + ((cnt * half) >> 1), hi = o0 + ((cnt * (half + 1)) >> 1);     \
    int subcnt = hi - lo;                                                       \
    float inv = 1.0f / ((float)cnt * 64.0f);                                    \
    const float* pp = &g_pooled[(size_t)r * BB * BINS];                         \
    float p0 = pp[lane], p1 = pp[lane + 32], p2 = (lane < 16) ? pp[lane + 64] : 0.0f; \
    ull a2[BB][2];                                                              \
    _Pragma("unroll")                                                           \
    for (int b = 0; b < BB; b++) {                                              \
        a2[b][0] = bb2[0]; a2[b][1] = bb2[1];                                   \
        _Pragma("unroll")                                                       \
        for (int j = 0; j < BINS; j++) {                                        \
            int idx = b * BINS + j;                                             \
            float v = __shfl_sync(0xffffffffu, idx < 32 ? p0 : (idx < 64 ? p1 : p2), idx & 31); \
            float pm = v * inv;                                                 \
            ull pm2 = pk2(pm, pm);                                              \
            a2[b][0] = fma2(pm2, w1p2[j][0], a2[b][0]);                         \
            a2[b][1] = fma2(pm2, w1p2[j][1], a2[b][1]);                         \
        }                                                                       \
    }

// ---------------- K2: stats + (last block) layernorm fold ----------------
// Two warps per residue; all 8 batches share cond loads.
__global__ void __launch_bounds__(128) k_stats(const float* __restrict__ cond,
                                               const float* __restrict__ W1,
                                               const float* __restrict__ b1,
                                               const float* __restrict__ gamma,
                                               const float* __restrict__ beta,
                                               const float* __restrict__ W2,
                                               const float* __restrict__ b2) {
    __shared__ float ssum[HID];
    __shared__ float ssq[HID];
    __shared__ bool is_last;
    int t = threadIdx.x;
    ssum[t] = 0.0f; ssq[t] = 0.0f;
    __syncthreads();
    int lane = t & 31;

    LOAD_W1_PACKED();

    ull ls2[2] = {0, 0}, lq2[2] = {0, 0};
    int wg = (blockIdx.x * blockDim.x + t) >> 5;   // 0 .. 2*RR-1
    int r = wg >> 1, half = wg & 1;
    if (r < RR) {
        COMPUTE_A2();
        float cseg = (lane < 3 * subcnt) ? __ldg(&cond[lo * 3 + lane]) : 0.0f;
        for (int i = 0; i < subcnt; i++) {
            float c0 = __shfl_sync(0xffffffffu, cseg, 3 * i);
            float c1 = __shfl_sync(0xffffffffu, cseg, 3 * i + 1);
            float c2 = __shfl_sync(0xffffffffu, cseg, 3 * i + 2);
            ull c02 = pk2(c0, c0), c12 = pk2(c1, c1), c22 = pk2(c2, c2);
#pragma unroll
            for (int k2 = 0; k2 < 2; k2++) {
                ull cc = fma2(c02, w1c2[0][k2], fma2(c12, w1c2[1][k2], mul2(c22, w1c2[2][k2])));
#pragma unroll
                for (int b = 0; b < BB; b++) {
                    ull v = relu2(add2(a2[b][k2], cc));
                    ls2[k2] = add2(ls2[k2], v);
                    lq2[k2] = fma2(v, v, lq2[k2]);
                }
            }
        }
    }
    float x0, x1;
    upk2(ls2[0], x0, x1); atomicAdd(&ssum[lane], x0); atomicAdd(&ssum[lane + 32], x1);
    upk2(ls2[1], x0, x1); atomicAdd(&ssum[lane + 64], x0); atomicAdd(&ssum[lane + 96], x1);
    upk2(lq2[0], x0, x1); atomicAdd(&ssq[lane], x0);  atomicAdd(&ssq[lane + 32], x1);
    upk2(lq2[1], x0, x1); atomicAdd(&ssq[lane + 64], x0); atomicAdd(&ssq[lane + 96], x1);
    __syncthreads();
    atomicAdd(&g_sum[t], ssum[t]);
    atomicAdd(&g_sumsq[t], ssq[t]);

    // -------- last-block tail: fold layernorm into W2/b2 (no extra launch) ----
    __threadfence();
    if (t == 0) is_last = (atomicAdd(&g_done, 1u) == gridDim.x - 1);
    __syncthreads();
    if (!is_last) return;

    int f = t;
    const float invn = 1.0f / (float)(BB * NN);
    float mu = g_sum[f] * invn;
    float var = g_sumsq[f] * invn - mu * mu;
    float s = rsqrtf(var + EPSV) * __ldg(&gamma[f]);
    float off = __ldg(&beta[f]) - mu * s;
    float w0 = __ldg(&W2[f * 3 + 0]), w1 = __ldg(&W2[f * 3 + 1]), w2 = __ldg(&W2[f * 3 + 2]);
    g_W2p[f * 3 + 0] = w0 * s;
    g_W2p[f * 3 + 1] = w1 * s;
    g_W2p[f * 3 + 2] = w2 * s;

    // reuse ssum/ssq smem for the 3-way reduction
    ssum[f] = off * w0; ssq[f] = off * w1;
    __shared__ float red2[HID];
    red2[f] = off * w2;
    __syncthreads();
    for (int st = 64; st >= 1; st >>= 1) {
        if (f < st) {
            ssum[f] += ssum[f + st];
            ssq[f] += ssq[f + st];
            red2[f] += red2[f + st];
        }
        __syncthreads();
    }
    if (f == 0) {
        g_b2p[0] = __ldg(&b2[0]) + ssum[0];
        g_b2p[1] = __ldg(&b2[1]) + ssq[0];
        g_b2p[2] = __ldg(&b2[2]) + red2[0];
        g_done = 0;   // reset for next graph replay (deterministic)
    }
}

// ---------------- K3: output = relu(h) @ W2p + b2p ----------------
// Two warps per residue; packed-pair butterfly reduction.
__global__ void __launch_bounds__(128) k_out(const float* __restrict__ cond,
                                             const float* __restrict__ W1,
                                             const float* __restrict__ b1,
                                             float* __restrict__ out) {
    int t = threadIdx.x, lane = t & 31;

    ull w22[2][3];
#pragma unroll
    for (int k2 = 0; k2 < 2; k2++)
#pragma unroll
        for (int j = 0; j < 3; j++)
            w22[k2][j] = pk2(g_W2p[(lane + 64 * k2) * 3 + j],
                             g_W2p[(lane + 32 + 64 * k2) * 3 + j]);
    float bo0 = g_b2p[0], bo1 = g_b2p[1], bo2 = g_b2p[2];

    LOAD_W1_PACKED();

    int wg = (blockIdx.x * blockDim.x + t) >> 5;
    int r = wg >> 1, half = wg & 1;
    if (r >= RR) return;
    COMPUTE_A2();
    float cseg = (lane < 3 * subcnt) ? __ldg(&cond[lo * 3 + lane]) : 0.0f;

    for (int i = 0; i < subcnt; i++) {
        float c0 = __shfl_sync(0xffffffffu, cseg, 3 * i);
        float c1 = __shfl_sync(0xffffffffu, cseg, 3 * i + 1);
        float c2 = __shfl_sync(0xffffffffu, cseg, 3 * i + 2);
        ull c02 = pk2(c0, c0), c12 = pk2(c1, c1), c22 = pk2(c2, c2);
        ull cc[2];
#pragma unroll
        for (int k2 = 0; k2 < 2; k2++)
            cc[k2] = fma2(c02, w1c2[0][k2], fma2(c12, w1c2[1][k2], mul2(c22, w1c2[2][k2])));

        // process batches in 2 groups of 4 to bound live registers
#pragma unroll
        for (int g = 0; g < 2; g++) {
            // y01[q] = packed (r0, r1) for batch g*4+q ; y2 packed across batch pairs
            ull y01[4];
            ull y2p[2];
#pragma unroll
            for (int q = 0; q < 4; q++) {
                int b = g * 4 + q;
                ull s0 = 0, s1 = 0, s2 = 0;
#pragma unroll
                for (int k2 = 0; k2 < 2; k2++) {
                    ull v = relu2(add2(a2[b][k2], cc[k2]));
                    s0 = fma2(v, w22[k2][0], s0);
                    s1 = fma2(v, w22[k2][1], s1);
                    s2 = fma2(v, w22[k2][2], s2);
                }
                float u0, u1, r0, r1, r2;
                upk2(s0, u0, u1); r0 = u0 + u1;
                upk2(s1, u0, u1); r1 = u0 + u1;
                upk2(s2, u0, u1); r2 = u0 + u1;
                y01[q] = pk2(r0, r1);
                if (q & 1) {
                    float prev_lo, prev_hi; upk2(y2p[q >> 1], prev_lo, prev_hi);
                    y2p[q >> 1] = pk2(prev_lo, r2);
                } else {
                    y2p[q >> 1] = pk2(r2, 0.0f);
                }
            }
            // packed butterfly: 6 ull regs, add2 per level
#pragma unroll
            for (int o = 16; o >= 1; o >>= 1) {
#pragma unroll
                for (int q = 0; q < 4; q++)
                    y01[q] = add2(y01[q], __shfl_down_sync(0xffffffffu, y01[q], o));
#pragma unroll
                for (int q = 0; q < 2; q++)
                    y2p[q] = add2(y2p[q], __shfl_down_sync(0xffffffffu, y2p[q], o));
            }
            if (lane == 0) {
#pragma unroll
                for (int q = 0; q < 4; q++) {
                    int b = g * 4 + q;
                    float r0, r1, r2, rlo, rhi;
                    upk2(y01[q], r0, r1);
                    upk2(y2p[q >> 1], rlo, rhi);
                    r2 = (q & 1) ? rhi : rlo;
                    float* p = out + ((size_t)b * NN + (lo + i)) * 3;
                    p[0] = r0 + bo0;
                    p[1] = r1 + bo1;
                    p[2] = r2 + bo2;
                }
            }
        }
    }
}

// ---------------- launcher ----------------
extern "C" void kernel_launch(void* const* d_in, const int* in_sizes, int n_in,
                              void* d_out, int out_size) {
    const float* x     = (const float*)d_in[0];
    const float* cond  = (const float*)d_in[1];
    const int*   resid = (const int*)d_in[2];
    const float* W1    = (const float*)d_in[3];
    const float* b1    = (const float*)d_in[4];
    const float* gamma = (const float*)d_in[5];
    const float* beta  = (const float*)d_in[6];
    const float* W2    = (const float*)d_in[7];
    const float* b2    = (const float*)d_in[8];
    float* out = (float*)d_out;

    (void)in_sizes; (void)n_in; (void)out_size;

    k_init<<<(RR * BB * BINS + 255) / 256, 256>>>(resid);
    k_pool<<<(BB * NN + 7) / 8, 256>>>((const float4*)x, resid);
    k_stats<<<(2 * RR * 32 + 127) / 128, 128>>>(cond, W1, b1, gamma, beta, W2, b2);
    k_out<<<(2 * RR * 32 + 127) / 128, 128>>>(cond, W1, b1, out);
}

// round 7
// speedup vs baseline: 1.1076x; 1.0473x over previous
#include <cuda_runtime.h>

#define BB 8
#define NN 20000
#define DD 640
#define RR 2500
#define BINS 10
#define HID 128
#define EPSV 1e-5f
#define NB 444              // persistent grid: 3 blocks/SM on 148 SMs
#define NWARPS (NB * 4)

typedef unsigned long long ull;

// ---------------- scratch (no allocation allowed) ----------------
__device__ float g_pooled[RR * BB * BINS];   // [r][b][bin] segment sums
__device__ int   g_off[RR + 1];              // segment offsets (res_id sorted)
__device__ float g_sum[HID];
__device__ float g_sumsq[HID];
__device__ unsigned int g_done;              // phase barrier (zeroed by k_init)

// ---------------- packed f32x2 helpers (sm_100+) ----------------
__device__ __forceinline__ ull pk2(float lo, float hi) {
    ull r; asm("mov.b64 %0,{%1,%2};" : "=l"(r) : "f"(lo), "f"(hi)); return r;
}
__device__ __forceinline__ void upk2(ull v, float& lo, float& hi) {
    asm("mov.b64 {%0,%1},%2;" : "=f"(lo), "=f"(hi) : "l"(v));
}
__device__ __forceinline__ ull add2(ull a, ull b) {
    ull d; asm("add.rn.f32x2 %0,%1,%2;" : "=l"(d) : "l"(a), "l"(b)); return d;
}
__device__ __forceinline__ ull mul2(ull a, ull b) {
    ull d; asm("mul.rn.f32x2 %0,%1,%2;" : "=l"(d) : "l"(a), "l"(b)); return d;
}
__device__ __forceinline__ ull fma2(ull a, ull b, ull c) {
    ull d; asm("fma.rn.f32x2 %0,%1,%2,%3;" : "=l"(d) : "l"(a), "l"(b), "l"(c)); return d;
}
__device__ __forceinline__ ull relu2(ull a) {
    float lo, hi; upk2(a, lo, hi);
    return pk2(fmaxf(lo, 0.0f), fmaxf(hi, 0.0f));
}

// ---------------- K0: zero accumulators + segment offsets ----------------
__global__ void k_init(const int* __restrict__ res_id) {
    int i = blockIdx.x * blockDim.x + threadIdx.x;
    if (i < RR * BB * BINS) g_pooled[i] = 0.0f;
    if (i < NN) {
        int r = res_id[i];
        if (i == 0 || res_id[i - 1] != r) g_off[r] = i;
    }
    if (i == 0) { g_off[RR] = NN; g_done = 0; }
    if (i < HID) { g_sum[i] = 0.0f; g_sumsq[i] = 0.0f; }
}

// ---------------- K1: pooling (dominant, reads all 410MB of x) ----------------
__global__ void k_pool(const float4* __restrict__ x4, const int* __restrict__ res_id) {
    int w = (blockIdx.x * blockDim.x + threadIdx.x) >> 5;
    int lane = threadIdx.x & 31;
    if (w >= BB * NN) return;
    int b = w / NN;
    int n = w - b * NN;
    int rid = res_id[n];
    const float4* row = x4 + (size_t)w * (DD / 4);

    float s[5];
#pragma unroll
    for (int k = 0; k < 5; k++) {
        float4 v = __ldcs(&row[lane + 32 * k]);   // read-once: evict-first
        s[k] = (v.x + v.y) + (v.z + v.w);
    }
#pragma unroll
    for (int k = 0; k < 5; k++) {
#pragma unroll
        for (int off = 8; off >= 1; off >>= 1)
            s[k] += __shfl_down_sync(0xffffffffu, s[k], off, 16);
    }
    if ((lane & 15) == 0) {
        int half = lane >> 4;
        float* dst = &g_pooled[((size_t)rid * BB + b) * BINS];
#pragma unroll
        for (int k = 0; k < 5; k++)
            atomicAdd(&dst[2 * k + half], s[k]);
    }
}

// Per-residue a2[b][k2] using smem-resident packed W1; warp handles [lo,hi)
// (its half of the residue's atom range).
#define COMPUTE_A2_SMEM()                                                       \
    int o0 = g_off[r], o1 = g_off[r + 1], cnt = o1 - o0;                        \
    int lo = o0 + ((cnt * half) >> 1), hi = o0 + ((cnt * (half + 1)) >> 1);     \
    int subcnt = hi - lo;                                                       \
    float inv = 1.0f / ((float)cnt * 64.0f);                                    \
    const float* pp = &g_pooled[(size_t)r * BB * BINS];                         \
    float p0 = pp[lane], p1 = pp[lane + 32], p2 = (lane < 16) ? pp[lane + 64] : 0.0f; \
    ull a2[BB][2];                                                              \
    _Pragma("unroll")                                                           \
    for (int b = 0; b < BB; b++) { a2[b][0] = bb2[0]; a2[b][1] = bb2[1]; }      \
    _Pragma("unroll")                                                           \
    for (int j = 0; j < BINS; j++) {                                            \
        ull wj0 = s_w1p[j][0][lane], wj1 = s_w1p[j][1][lane];                   \
        _Pragma("unroll")                                                       \
        for (int b = 0; b < BB; b++) {                                          \
            int idx = b * BINS + j;                                             \
            float v = __shfl_sync(0xffffffffu, idx < 32 ? p0 : (idx < 64 ? p1 : p2), idx & 31); \
            float pm = v * inv;                                                 \
            ull pm2 = pk2(pm, pm);                                              \
            a2[b][0] = fma2(pm2, wj0, a2[b][0]);                                \
            a2[b][1] = fma2(pm2, wj1, a2[b][1]);                                \
        }                                                                       \
    }

// ---------------- K2: persistent fused stats + fold + output ----------------
__global__ void __launch_bounds__(128, 4) k_fused(
        const float* __restrict__ cond, const float* __restrict__ W1,
        const float* __restrict__ b1, const float* __restrict__ gamma,
        const float* __restrict__ beta, const float* __restrict__ W2,
        const float* __restrict__ b2, float* __restrict__ out) {
    __shared__ ull s_w1p[BINS][2][32];   // packed pooled-part of W1 (5KB)
    __shared__ float ssum[HID];
    __shared__ float ssq[HID];
    int t = threadIdx.x, lane = t & 31;

    // cooperative pack of W1[0:10] into smem
    for (int e = t; e < BINS * 64; e += 128) {
        int j = e >> 6, k2 = (e >> 5) & 1, l = e & 31;
        int f = l + 64 * k2;
        s_w1p[j][k2][l] = pk2(__ldg(&W1[j * HID + f]), __ldg(&W1[j * HID + f + 32]));
    }
    ssum[t] = 0.0f; ssq[t] = 0.0f;

    // conditioner part + bias in registers (feature pairing (f, f+32))
    ull w1c2[3][2], bb2[2];
#pragma unroll
    for (int j = 0; j < 3; j++) {
        w1c2[j][0] = pk2(__ldg(&W1[(BINS + j) * HID + lane]), __ldg(&W1[(BINS + j) * HID + lane + 32]));
        w1c2[j][1] = pk2(__ldg(&W1[(BINS + j) * HID + lane + 64]), __ldg(&W1[(BINS + j) * HID + lane + 96]));
    }
    bb2[0] = pk2(__ldg(&b1[lane]), __ldg(&b1[lane + 32]));
    bb2[1] = pk2(__ldg(&b1[lane + 64]), __ldg(&b1[lane + 96]));
    __syncthreads();

    int warp0 = (blockIdx.x * blockDim.x + t) >> 5;

    // ================= phase 1: stats =================
    ull ls2[2] = {0, 0}, lq2[2] = {0, 0};
    for (int task = warp0; task < 2 * RR; task += NWARPS) {
        int r = task >> 1, half = task & 1;
        COMPUTE_A2_SMEM();
        float cseg = (lane < 3 * subcnt) ? __ldg(&cond[lo * 3 + lane]) : 0.0f;
        for (int i = 0; i < subcnt; i++) {
            float c0 = __shfl_sync(0xffffffffu, cseg, 3 * i);
            float c1 = __shfl_sync(0xffffffffu, cseg, 3 * i + 1);
            float c2 = __shfl_sync(0xffffffffu, cseg, 3 * i + 2);
            ull c02 = pk2(c0, c0), c12 = pk2(c1, c1), c22 = pk2(c2, c2);
#pragma unroll
            for (int k2 = 0; k2 < 2; k2++) {
                ull cc = fma2(c02, w1c2[0][k2], fma2(c12, w1c2[1][k2], mul2(c22, w1c2[2][k2])));
#pragma unroll
                for (int b = 0; b < BB; b++) {
                    ull v = relu2(add2(a2[b][k2], cc));
                    ls2[k2] = add2(ls2[k2], v);
                    lq2[k2] = fma2(v, v, lq2[k2]);
                }
            }
        }
    }
    {
        float x0, x1;
        upk2(ls2[0], x0, x1); atomicAdd(&ssum[lane], x0); atomicAdd(&ssum[lane + 32], x1);
        upk2(ls2[1], x0, x1); atomicAdd(&ssum[lane + 64], x0); atomicAdd(&ssum[lane + 96], x1);
        upk2(lq2[0], x0, x1); atomicAdd(&ssq[lane], x0);  atomicAdd(&ssq[lane + 32], x1);
        upk2(lq2[1], x0, x1); atomicAdd(&ssq[lane + 64], x0); atomicAdd(&ssq[lane + 96], x1);
    }
    __syncthreads();
    atomicAdd(&g_sum[t], ssum[t]);
    atomicAdd(&g_sumsq[t], ssq[t]);
    __syncthreads();

    // ================= phase barrier (all blocks resident by construction) ====
    __threadfence();
    if (t == 0) {
        atomicAdd(&g_done, 1u);
        while (atomicAdd(&g_done, 0u) < (unsigned)gridDim.x) __nanosleep(64);
    }
    __syncthreads();
    __threadfence();

    // ================= per-warp layernorm fold =================
    ull w22[2][3];
    float bo0, bo1, bo2;
    {
        const float invn = 1.0f / (float)(BB * NN);
        float w2s[4][3];
        float offc[3] = {0, 0, 0};
#pragma unroll
        for (int k = 0; k < 4; k++) {
            int f = lane + 32 * k;
            float mu = g_sum[f] * invn;
            float var = g_sumsq[f] * invn - mu * mu;
            float s = rsqrtf(var + EPSV) * __ldg(&gamma[f]);
            float off = __ldg(&beta[f]) - mu * s;
#pragma unroll
            for (int j = 0; j < 3; j++) {
                float w = __ldg(&W2[f * 3 + j]);
                w2s[k][j] = w * s;
                offc[j] += off * w;
            }
        }
#pragma unroll
        for (int o = 16; o >= 1; o >>= 1) {
            offc[0] += __shfl_xor_sync(0xffffffffu, offc[0], o);
            offc[1] += __shfl_xor_sync(0xffffffffu, offc[1], o);
            offc[2] += __shfl_xor_sync(0xffffffffu, offc[2], o);
        }
        bo0 = offc[0] + __ldg(&b2[0]);
        bo1 = offc[1] + __ldg(&b2[1]);
        bo2 = offc[2] + __ldg(&b2[2]);
#pragma unroll
        for (int j = 0; j < 3; j++) {
            w22[0][j] = pk2(w2s[0][j], w2s[1][j]);
            w22[1][j] = pk2(w2s[2][j], w2s[3][j]);
        }
    }

    // ================= phase 2: output =================
    for (int task = warp0; task < 2 * RR; task += NWARPS) {
        int r = task >> 1, half = task & 1;
        COMPUTE_A2_SMEM();
        float cseg = (lane < 3 * subcnt) ? __ldg(&cond[lo * 3 + lane]) : 0.0f;

        for (int i = 0; i < subcnt; i++) {
            float c0 = __shfl_sync(0xffffffffu, cseg, 3 * i);
            float c1 = __shfl_sync(0xffffffffu, cseg, 3 * i + 1);
            float c2 = __shfl_sync(0xffffffffu, cseg, 3 * i + 2);
            ull c02 = pk2(c0, c0), c12 = pk2(c1, c1), c22 = pk2(c2, c2);
            ull cc[2];
#pragma unroll
            for (int k2 = 0; k2 < 2; k2++)
                cc[k2] = fma2(c02, w1c2[0][k2], fma2(c12, w1c2[1][k2], mul2(c22, w1c2[2][k2])));

#pragma unroll
            for (int g = 0; g < 2; g++) {
                ull y01[4];
                ull y2p[2];
#pragma unroll
                for (int q = 0; q < 4; q++) {
                    int b = g * 4 + q;
                    ull s0 = 0, s1 = 0, s2 = 0;
#pragma unroll
                    for (int k2 = 0; k2 < 2; k2++) {
                        ull v = relu2(add2(a2[b][k2], cc[k2]));
                        s0 = fma2(v, w22[k2][0], s0);
                        s1 = fma2(v, w22[k2][1], s1);
                        s2 = fma2(v, w22[k2][2], s2);
                    }
                    float u0, u1, r0, r1, r2;
                    upk2(s0, u0, u1); r0 = u0 + u1;
                    upk2(s1, u0, u1); r1 = u0 + u1;
                    upk2(s2, u0, u1); r2 = u0 + u1;
                    y01[q] = pk2(r0, r1);
                    if (q & 1) {
                        float plo, phi; upk2(y2p[q >> 1], plo, phi);
                        y2p[q >> 1] = pk2(plo, r2);
                    } else {
                        y2p[q >> 1] = pk2(r2, 0.0f);
                    }
                }
#pragma unroll
                for (int o = 16; o >= 1; o >>= 1) {
#pragma unroll
                    for (int q = 0; q < 4; q++)
                        y01[q] = add2(y01[q], __shfl_down_sync(0xffffffffu, y01[q], o));
#pragma unroll
                    for (int q = 0; q < 2; q++)
                        y2p[q] = add2(y2p[q], __shfl_down_sync(0xffffffffu, y2p[q], o));
                }
                if (lane == 0) {
#pragma unroll
                    for (int q = 0; q < 4; q++) {
                        int b = g * 4 + q;
                        float r0, r1, r2, rlo, rhi;
                        upk2(y01[q], r0, r1);
                        upk2(y2p[q >> 1], rlo, rhi);
                        r2 = (q & 1) ? rhi : rlo;
                        float* p = out + ((size_t)b * NN + (lo + i)) * 3;
                        p[0] = r0 + bo0;
                        p[1] = r1 + bo1;
                        p[2] = r2 + bo2;
                    }
                }
            }
        }
    }
}

// ---------------- launcher ----------------
extern "C" void kernel_launch(void* const* d_in, const int* in_sizes, int n_in,
                              void* d_out, int out_size) {
    const float* x     = (const float*)d_in[0];
    const float* cond  = (const float*)d_in[1];
    const int*   resid = (const int*)d_in[2];
    const float* W1    = (const float*)d_in[3];
    const float* b1    = (const float*)d_in[4];
    const float* gamma = (const float*)d_in[5];
    const float* beta  = (const float*)d_in[6];
    const float* W2    = (const float*)d_in[7];
    const float* b2    = (const float*)d_in[8];
    float* out = (float*)d_out;

    (void)in_sizes; (void)n_in; (void)out_size;

    k_init<<<(RR * BB * BINS + 255) / 256, 256>>>(resid);
    k_pool<<<(BB * NN + 7) / 8, 256>>>((const float4*)x, resid);
    k_fused<<<NB, 128>>>(cond, W1, b1, gamma, beta, W2, b2, out);
}